// round 3
// baseline (speedup 1.0000x reference)
#include <cuda_runtime.h>
#include <cuda_bf16.h>
#include <math.h>
#include <stdint.h>

// ---------------------------------------------------------------------------
// HyperGRUCell: 6 GEMMs (4096x1024x1024) + fused per-row hyperbolic chain.
// Round 2: tensor-core GEMM via mma.sync m16n8k16 bf16 with 3-term bf16
//          split (hi/lo) for fp32-grade accuracy. Fused chain unchanged.
// ---------------------------------------------------------------------------

#define GB 4096   // batch
#define GH 1024   // hidden == input dim
#define GK 1024   // reduction dim

// Scratch for the 6 GEMM outputs, 96 MB (device global: allowed, no alloc).
__device__ float g_mm[6ull * GB * GH];

// ---------------------------------------------------------------------------
// Tensor-core batched GEMM.  C[z] = A[z] @ W[z]
// Block tile 128x128, BK=16, 256 threads (8 warps, 4x2), warp tile 32x64.
// Fragments per PTX m16n8k16 layout, loaded with scalar LDS (conflict-free
// via k-dim padding to 24 bf16).
// ---------------------------------------------------------------------------

__device__ __forceinline__ void mma_bf16(float* c, const uint32_t* a, const uint32_t* b) {
    asm volatile(
        "mma.sync.aligned.m16n8k16.row.col.f32.bf16.bf16.f32 "
        "{%0,%1,%2,%3}, {%4,%5,%6,%7}, {%8,%9}, {%0,%1,%2,%3};\n"
        : "+f"(c[0]), "+f"(c[1]), "+f"(c[2]), "+f"(c[3])
        : "r"(a[0]), "r"(a[1]), "r"(a[2]), "r"(a[3]), "r"(b[0]), "r"(b[1]));
}

#define LDK 24   // padded k-stride in bf16 elements (16 data + 8 pad)

__global__ __launch_bounds__(256) void gemm6_mma_kernel(
    const float* __restrict__ inp, const float* __restrict__ ph,
    const float* __restrict__ wiz, const float* __restrict__ whz,
    const float* __restrict__ wir, const float* __restrict__ whr,
    const float* __restrict__ wih, const float* __restrict__ whh)
{
    const int z = blockIdx.z;
    const float* __restrict__ A = (z & 1) ? ph : inp;
    const float* __restrict__ W;
    switch (z) {
        case 0: W = wiz; break; case 1: W = whz; break;
        case 2: W = wir; break; case 3: W = whr; break;
        case 4: W = wih; break; default: W = whh; break;
    }
    float* __restrict__ C = g_mm + (size_t)z * GB * GH;

    const int bm = blockIdx.y * 128;
    const int bn = blockIdx.x * 128;

    // hi/lo split tiles; [row][k] with k contiguous (padded to LDK).
    __shared__ __nv_bfloat16 Ah[128][LDK], Al[128][LDK];
    __shared__ __nv_bfloat16 Bh[128][LDK], Bl[128][LDK];   // [n][k] (transposed)

    const int tid   = threadIdx.x;
    const int lane  = tid & 31;
    const int wrp   = tid >> 5;          // 0..7
    const int wm    = (wrp & 3) * 32;    // warp m offset
    const int wn    = (wrp >> 2) * 64;   // warp n offset
    const int gid   = lane >> 2;         // 0..7
    const int tig   = lane & 3;          // 0..3

    // staging coordinates (2 float4 per thread for each of A and B)
    // A tile: 128 rows x 16 k -> 512 float4 ; lin = tid + 256*f
    const int arow0 = tid >> 2,          acq0 = (tid & 3) * 4;
    const int arow1 = (tid + 256) >> 2,  acq1 = acq0;          // same colq pattern
    // B tile: 16 k-rows x 128 n -> 512 float4
    const int bkr0 = tid >> 5,           bnq0 = (tid & 31) * 4;
    const int bkr1 = (tid + 256) >> 5,   bnq1 = bnq0;

    float acc[2][8][4];
    #pragma unroll
    for (int mi = 0; mi < 2; mi++)
        #pragma unroll
        for (int ni = 0; ni < 8; ni++)
            #pragma unroll
            for (int r = 0; r < 4; r++) acc[mi][ni][r] = 0.f;

    float4 va0, va1, vb0, vb1;

    // helper lambda-ish macros for staging
    #define LOAD_TILE(kt)                                                        \
        va0 = *(const float4*)(A + (size_t)(bm + arow0) * GK + (kt)*16 + acq0);  \
        va1 = *(const float4*)(A + (size_t)(bm + arow1) * GK + (kt)*16 + acq1);  \
        vb0 = *(const float4*)(W + (size_t)((kt)*16 + bkr0) * GH + bn + bnq0);   \
        vb1 = *(const float4*)(W + (size_t)((kt)*16 + bkr1) * GH + bn + bnq1);

    #define STORE_TILE()                                                          \
        {                                                                         \
            const float af[8] = { va0.x, va0.y, va0.z, va0.w,                     \
                                  va1.x, va1.y, va1.z, va1.w };                   \
            _Pragma("unroll")                                                     \
            for (int j = 0; j < 4; j++) {                                         \
                __nv_bfloat16 hi = __float2bfloat16(af[j]);                       \
                __nv_bfloat16 lo = __float2bfloat16(af[j] - __bfloat162float(hi));\
                Ah[arow0][acq0 + j] = hi;  Al[arow0][acq0 + j] = lo;              \
            }                                                                     \
            _Pragma("unroll")                                                     \
            for (int j = 0; j < 4; j++) {                                         \
                __nv_bfloat16 hi = __float2bfloat16(af[4 + j]);                   \
                __nv_bfloat16 lo = __float2bfloat16(af[4+j] - __bfloat162float(hi));\
                Ah[arow1][acq1 + j] = hi;  Al[arow1][acq1 + j] = lo;              \
            }                                                                     \
            const float bf[8] = { vb0.x, vb0.y, vb0.z, vb0.w,                     \
                                  vb1.x, vb1.y, vb1.z, vb1.w };                   \
            _Pragma("unroll")                                                     \
            for (int j = 0; j < 4; j++) {                                         \
                __nv_bfloat16 hi = __float2bfloat16(bf[j]);                       \
                __nv_bfloat16 lo = __float2bfloat16(bf[j] - __bfloat162float(hi));\
                Bh[bnq0 + j][bkr0] = hi;  Bl[bnq0 + j][bkr0] = lo;                \
            }                                                                     \
            _Pragma("unroll")                                                     \
            for (int j = 0; j < 4; j++) {                                         \
                __nv_bfloat16 hi = __float2bfloat16(bf[4 + j]);                   \
                __nv_bfloat16 lo = __float2bfloat16(bf[4+j] - __bfloat162float(hi));\
                Bh[bnq1 + j][bkr1] = hi;  Bl[bnq1 + j][bkr1] = lo;                \
            }                                                                     \
        }

    LOAD_TILE(0);
    STORE_TILE();
    __syncthreads();

    const int NT = GK / 16;   // 64 k-tiles
    for (int kt = 0; kt < NT; kt++) {
        const bool more = (kt + 1) < NT;
        if (more) { LOAD_TILE(kt + 1); }   // global prefetch overlaps MMAs

        // ---- load fragments from smem -----------------------------------
        uint32_t afh[2][4], afl[2][4];
        #pragma unroll
        for (int mi = 0; mi < 2; mi++) {
            const int r0 = wm + mi * 16 + gid;
            afh[mi][0] = *(const uint32_t*)&Ah[r0    ][2 * tig];
            afh[mi][1] = *(const uint32_t*)&Ah[r0 + 8][2 * tig];
            afh[mi][2] = *(const uint32_t*)&Ah[r0    ][2 * tig + 8];
            afh[mi][3] = *(const uint32_t*)&Ah[r0 + 8][2 * tig + 8];
            afl[mi][0] = *(const uint32_t*)&Al[r0    ][2 * tig];
            afl[mi][1] = *(const uint32_t*)&Al[r0 + 8][2 * tig];
            afl[mi][2] = *(const uint32_t*)&Al[r0    ][2 * tig + 8];
            afl[mi][3] = *(const uint32_t*)&Al[r0 + 8][2 * tig + 8];
        }
        uint32_t bfh[8][2], bfl[8][2];
        #pragma unroll
        for (int ni = 0; ni < 8; ni++) {
            const int nr = wn + ni * 8 + gid;
            bfh[ni][0] = *(const uint32_t*)&Bh[nr][2 * tig];
            bfh[ni][1] = *(const uint32_t*)&Bh[nr][2 * tig + 8];
            bfl[ni][0] = *(const uint32_t*)&Bl[nr][2 * tig];
            bfl[ni][1] = *(const uint32_t*)&Bl[nr][2 * tig + 8];
        }

        // ---- 3-term split MMAs ------------------------------------------
        #pragma unroll
        for (int mi = 0; mi < 2; mi++)
            #pragma unroll
            for (int ni = 0; ni < 8; ni++) {
                mma_bf16(acc[mi][ni], afh[mi], bfh[ni]);
                mma_bf16(acc[mi][ni], afh[mi], bfl[ni]);
                mma_bf16(acc[mi][ni], afl[mi], bfh[ni]);
            }

        __syncthreads();           // all reads of smem done
        if (more) { STORE_TILE(); }
        __syncthreads();           // stores visible
    }

    // ---- epilogue -------------------------------------------------------
    #pragma unroll
    for (int mi = 0; mi < 2; mi++) {
        const int row = bm + wm + mi * 16 + gid;
        #pragma unroll
        for (int ni = 0; ni < 8; ni++) {
            const int col = bn + wn + ni * 8 + 2 * tig;
            *(float2*)(C + (size_t)row * GH + col) =
                make_float2(acc[mi][ni][0], acc[mi][ni][1]);
            *(float2*)(C + (size_t)(row + 8) * GH + col) =
                make_float2(acc[mi][ni][2], acc[mi][ni][3]);
        }
    }
    #undef LOAD_TILE
    #undef STORE_TILE
}

// ---------------------------------------------------------------------------
// Fused hyperbolic chain, one block per batch row, 1024 threads (1 elem each).
// ---------------------------------------------------------------------------

__device__ __forceinline__ float artanh_c(float v) {
    v = fminf(fmaxf(v, -1.0f + 1e-5f), 1.0f - 1e-5f);
    return 0.5f * (log1pf(v) - log1pf(-v));
}
__device__ __forceinline__ float clipn(float s) { return fmaxf(s, 1e-15f); }

template<int N>
__device__ __forceinline__ void breduce(float (&v)[N]) {
    __shared__ float sm[N][32];
    const int lane = threadIdx.x & 31;
    const int wid  = threadIdx.x >> 5;
    __syncthreads();
    #pragma unroll
    for (int i = 0; i < N; i++) {
        float x = v[i];
        #pragma unroll
        for (int o = 16; o > 0; o >>= 1) x += __shfl_down_sync(0xffffffffu, x, o);
        if (lane == 0) sm[i][wid] = x;
    }
    __syncthreads();
    if (wid == 0) {
        #pragma unroll
        for (int i = 0; i < N; i++) {
            float x = sm[i][lane];
            #pragma unroll
            for (int o = 16; o > 0; o >>= 1) x += __shfl_down_sync(0xffffffffu, x, o);
            if (lane == 0) sm[i][0] = x;
        }
    }
    __syncthreads();
    #pragma unroll
    for (int i = 0; i < N; i++) v[i] = sm[i][0];
}

__device__ __forceinline__ float madd_el(float a, float b,
                                         float xy, float x2, float y2) {
    float num = (1.0f + 2.0f * xy + y2) * a + (1.0f - x2) * b;
    float den = 1.0f + 2.0f * xy + x2 * y2;
    return num / den;
}

__global__ __launch_bounds__(1024) void fused_kernel(
    const float* __restrict__ inp, const float* __restrict__ prevh,
    const float* __restrict__ bz, const float* __restrict__ br,
    const float* __restrict__ bh, float* __restrict__ out)
{
    const int row = blockIdx.x;
    const int t   = threadIdx.x;
    const size_t off = (size_t)row * GH + t;
    const size_t S   = (size_t)GB * GH;

    const float x   = inp[off];
    const float h   = prevh[off];
    const float xWz = g_mm[0 * S + off], hWz = g_mm[1 * S + off];
    const float xWr = g_mm[2 * S + off], hWr = g_mm[3 * S + off];
    const float xWh = g_mm[4 * S + off], hWh = g_mm[5 * S + off];
    const float Bz = bz[t], Br = br[t], Bh = bh[t];

    // ---- batch 0: raw squared norms -------------------------------------
    float r0[8] = { x*x, h*h, xWz*xWz, hWz*hWz, xWr*xWr, hWr*hWr, xWh*xWh, hWh*hWh };
    breduce<8>(r0);
    const float x2r = r0[0], h2r = r0[1];
    const float x_n = sqrtf(clipn(x2r)), h_n = sqrtf(clipn(h2r));
    const float atx = artanh_c(x_n),     ath = artanh_c(h_n);

    const float n_xz = sqrtf(clipn(r0[2])), n_hz = sqrtf(clipn(r0[3]));
    const float n_xr = sqrtf(clipn(r0[4])), n_hr = sqrtf(clipn(r0[5]));
    const float n_xh = sqrtf(clipn(r0[6])), n_hh = sqrtf(clipn(r0[7]));
    const float f_xz = tanhf(n_xz / x_n * atx) / n_xz;
    const float f_hz = tanhf(n_hz / h_n * ath) / n_hz;
    const float f_xr = tanhf(n_xr / x_n * atx) / n_xr;
    const float f_hr = tanhf(n_hr / h_n * ath) / n_hr;
    const float f_xh = tanhf(n_xh / x_n * atx) / n_xh;
    const float f_hh = tanhf(n_hh / h_n * ath) / n_hh;

    const float a_z = f_hz * hWz;
    const float a_r = f_hr * hWr;
    const float a_h = f_hh * hWh;

    // ---- batch 1: inner mobius_add(mv_h*, bias) stats -------------------
    float r1[6] = { a_z*Bz, Bz*Bz, a_r*Br, Br*Br, a_h*Bh, Bh*Bh };
    breduce<6>(r1);
    const float x2_az = f_hz * f_hz * r0[3];
    const float x2_ar = f_hr * f_hr * r0[5];
    const float x2_ah = f_hh * f_hh * r0[7];
    const float iz = madd_el(a_z, Bz, r1[0], x2_az, r1[1]);
    const float ir = madd_el(a_r, Br, r1[2], x2_ar, r1[3]);
    const float hh = madd_el(a_h, Bh, r1[4], x2_ah, r1[5]);

    const float mvx_z = f_xz * xWz;
    const float mvx_r = f_xr * xWr;
    const float mvx_h = f_xh * xWh;

    // ---- batch 2: outer mobius_add stats + ||hh||^2 ---------------------
    float r2[5] = { mvx_z*iz, iz*iz, mvx_r*ir, ir*ir, hh*hh };
    breduce<5>(r2);
    const float x2_mxz = f_xz * f_xz * r0[2];
    const float x2_mxr = f_xr * f_xr * r0[4];
    const float u_z = madd_el(mvx_z, iz, r2[0], x2_mxz, r2[1]);
    const float u_r = madd_el(mvx_r, ir, r2[2], x2_mxr, r2[3]);
    const float hh2   = r2[4];
    const float hh_n  = sqrtf(clipn(hh2));
    const float at_hh = artanh_c(hh_n);

    // ---- batch 3: gate norms --------------------------------------------
    float r3[2] = { u_z*u_z, u_r*u_r };
    breduce<2>(r3);
    const float un_z = sqrtf(clipn(r3[0]));
    const float un_r = sqrtf(clipn(r3[1]));
    const float gz_f = artanh_c(un_z) / un_z;
    const float gr_f = artanh_c(un_r) / un_r;
    const float zg = 1.0f / (1.0f + expf(-gz_f * u_z));
    const float rg = 1.0f / (1.0f + expf(-gr_f * u_r));

    // ---- pointwise prod p = mpp(hh, r); batch 4 --------------------------
    const float ux = rg * hh;
    float r4[2] = { ux*ux, ux*mvx_h };
    breduce<2>(r4);
    const float uxn = sqrtf(clipn(r4[0]));
    const float gp  = tanhf(uxn / hh_n * at_hh) / uxn;
    const float p   = gp * ux;
    const float xy_t = gp * r4[1];
    const float x2_p = gp * gp * r4[0];
    const float y2_m = f_xh * f_xh * r0[6];
    const float temp = madd_el(p, mvx_h, xy_t, x2_p, y2_m);

    // ---- batch 5: minus_h = mobius_add(-h, temp) -------------------------
    float r5[2] = { h*temp, temp*temp };
    breduce<2>(r5);
    const float mh = madd_el(-h, temp, -r5[0], h2r, r5[1]);

    // ---- batch 6: q = mpp(minus_h, z); h_next = madd(h, q) ---------------
    const float uq = zg * mh;
    float r6[3] = { mh*mh, uq*uq, h*uq };
    breduce<3>(r6);
    const float mh_n  = sqrtf(clipn(r6[0]));
    const float at_mh = artanh_c(mh_n);
    const float uqn   = sqrtf(clipn(r6[1]));
    const float gq    = tanhf(uqn / mh_n * at_mh) / uqn;
    const float q     = gq * uq;

    const float xy_f = gq * r6[2];
    const float y2_q = gq * gq * r6[1];
    out[off] = madd_el(h, q, xy_f, h2r, y2_q);
}

// ---------------------------------------------------------------------------
extern "C" void kernel_launch(void* const* d_in, const int* in_sizes, int n_in,
                              void* d_out, int out_size)
{
    const float* inp   = (const float*)d_in[0];
    const float* prevh = (const float*)d_in[1];
    const float* wiz   = (const float*)d_in[2];
    const float* whz   = (const float*)d_in[3];
    const float* bz    = (const float*)d_in[4];
    const float* wir   = (const float*)d_in[5];
    const float* whr   = (const float*)d_in[6];
    const float* br    = (const float*)d_in[7];
    const float* wih   = (const float*)d_in[8];
    const float* whh   = (const float*)d_in[9];
    const float* bh    = (const float*)d_in[10];
    float* out = (float*)d_out;

    dim3 ggrid(GH / 128, GB / 128, 6);
    gemm6_mma_kernel<<<ggrid, 256>>>(inp, prevh, wiz, whz, wir, whr, wih, whh);
    fused_kernel<<<GB, 1024>>>(inp, prevh, bz, br, bh, out);
}

// round 8
// speedup vs baseline: 2.4169x; 2.4169x over previous
#include <cuda_runtime.h>
#include <cuda_bf16.h>
#include <math.h>
#include <stdint.h>

// ---------------------------------------------------------------------------
// HyperGRUCell. Round 8 (round-4 design, resubmitted — broker timeouts):
//  - GEMM: pre-converted bf16 hi/lo operands (weights pre-transposed),
//    double-buffered smem, mma.sync m16n8k16 3-term split (verified layout).
//  - Fused chain: collapsed from 7 block-reduction rounds to 3 via closed-form
//    Mobius algebra; 256 thr x 4 elem, float4 I/O.
// ---------------------------------------------------------------------------

#define GB 4096
#define GH 1024
#define GK 1024

__device__ float g_mm[6ull * GB * GH];                       // 96 MB scratch
__device__ __nv_bfloat16 g_Ah[2ull * GB * GK];               // inp/prev_h hi
__device__ __nv_bfloat16 g_Al[2ull * GB * GK];               // inp/prev_h lo
__device__ __nv_bfloat16 g_Wh[6ull * GK * GH];               // W^T hi  [n][k]
__device__ __nv_bfloat16 g_Wl[6ull * GK * GH];               // W^T lo  [n][k]

// ---------------------------------------------------------------------------
// Convert A matrices (inp, prev_h) fp32 -> bf16 hi/lo, same [m][k] layout.
// ---------------------------------------------------------------------------
__global__ __launch_bounds__(256) void conv_inputs(
    const float* __restrict__ inp, const float* __restrict__ ph)
{
    const int m = blockIdx.y;                       // 0=inp, 1=prev_h
    const size_t i = ((size_t)blockIdx.x * 256 + threadIdx.x) * 4;
    const float* src = m ? ph : inp;
    float4 v = *(const float4*)(src + i);
    const float f[4] = { v.x, v.y, v.z, v.w };
    __nv_bfloat16* dh = g_Ah + (size_t)m * GB * GK + i;
    __nv_bfloat16* dl = g_Al + (size_t)m * GB * GK + i;
    __nv_bfloat162 h2[2], l2[2];
    #pragma unroll
    for (int j = 0; j < 4; j++) {
        __nv_bfloat16 hi = __float2bfloat16(f[j]);
        __nv_bfloat16 lo = __float2bfloat16(f[j] - __bfloat162float(hi));
        ((__nv_bfloat16*)h2)[j] = hi;
        ((__nv_bfloat16*)l2)[j] = lo;
    }
    ((__nv_bfloat162*)dh)[0] = h2[0]; ((__nv_bfloat162*)dh)[1] = h2[1];
    ((__nv_bfloat162*)dl)[0] = l2[0]; ((__nv_bfloat162*)dl)[1] = l2[1];
}

// ---------------------------------------------------------------------------
// Convert + transpose weights: W[k][n] fp32 -> Wt[n][k] bf16 hi/lo.
// ---------------------------------------------------------------------------
__global__ __launch_bounds__(256) void conv_weights(
    const float* __restrict__ wiz, const float* __restrict__ whz,
    const float* __restrict__ wir, const float* __restrict__ whr,
    const float* __restrict__ wih, const float* __restrict__ whh)
{
    const int z = blockIdx.z;
    const float* __restrict__ W;
    switch (z) {
        case 0: W = wiz; break; case 1: W = whz; break;
        case 2: W = wir; break; case 3: W = whr; break;
        case 4: W = wih; break; default: W = whh; break;
    }
    __shared__ float tile[32][33];
    const int tx = threadIdx.x, ty = threadIdx.y;   // 32 x 8
    const int n0 = blockIdx.x * 32, k0 = blockIdx.y * 32;
    #pragma unroll
    for (int j = 0; j < 4; j++)
        tile[ty + 8 * j][tx] = W[(size_t)(k0 + ty + 8 * j) * GH + n0 + tx];
    __syncthreads();
    const size_t base = (size_t)z * GK * GH;
    #pragma unroll
    for (int j = 0; j < 4; j++) {
        const int n = n0 + ty + 8 * j;
        const int k = k0 + tx;
        float f = tile[tx][ty + 8 * j];
        __nv_bfloat16 hi = __float2bfloat16(f);
        __nv_bfloat16 lo = __float2bfloat16(f - __bfloat162float(hi));
        g_Wh[base + (size_t)n * GK + k] = hi;
        g_Wl[base + (size_t)n * GK + k] = lo;
    }
}

// ---------------------------------------------------------------------------
// Tensor-core GEMM: C[z] = A[z] @ W[z], operands pre-converted bf16 hi/lo.
// 128x128 tile, BK=16, 256 threads (8 warps 4x2, warp tile 32x64),
// double-buffered smem (48 KB), 1 barrier per k-tile.
// Fragment scheme identical to the verified round-3 kernel (LDK=24).
// ---------------------------------------------------------------------------
__device__ __forceinline__ void mma_bf16(float* c, const uint32_t* a, const uint32_t* b) {
    asm volatile(
        "mma.sync.aligned.m16n8k16.row.col.f32.bf16.bf16.f32 "
        "{%0,%1,%2,%3}, {%4,%5,%6,%7}, {%8,%9}, {%0,%1,%2,%3};\n"
        : "+f"(c[0]), "+f"(c[1]), "+f"(c[2]), "+f"(c[3])
        : "r"(a[0]), "r"(a[1]), "r"(a[2]), "r"(a[3]), "r"(b[0]), "r"(b[1]));
}

#define LDK 24

__global__ __launch_bounds__(256) void gemm6_v3(void)
{
    const int z = blockIdx.z;
    const __nv_bfloat16* __restrict__ Ahp = g_Ah + (size_t)(z & 1) * GB * GK;
    const __nv_bfloat16* __restrict__ Alp = g_Al + (size_t)(z & 1) * GB * GK;
    const __nv_bfloat16* __restrict__ Bhp = g_Wh + (size_t)z * GK * GH;
    const __nv_bfloat16* __restrict__ Blp = g_Wl + (size_t)z * GK * GH;
    float* __restrict__ C = g_mm + (size_t)z * GB * GH;

    const int bm = blockIdx.y * 128;
    const int bn = blockIdx.x * 128;

    __shared__ __nv_bfloat16 sAh[2][128][LDK], sAl[2][128][LDK];
    __shared__ __nv_bfloat16 sBh[2][128][LDK], sBl[2][128][LDK];   // 48 KB

    const int tid  = threadIdx.x;
    const int lane = tid & 31;
    const int wrp  = tid >> 5;
    const int wm   = (wrp & 3) * 32;
    const int wn   = (wrp >> 2) * 64;
    const int gid  = lane >> 2;
    const int tig  = lane & 3;

    // staging: each thread copies one 16B chunk per array per tile
    const int sr = tid >> 1;                // 0..127  row
    const int sc = (tid & 1) * 8;           // 0 or 8  k-offset (bf16 elems)

    float acc[2][8][4];
    #pragma unroll
    for (int mi = 0; mi < 2; mi++)
        #pragma unroll
        for (int ni = 0; ni < 8; ni++)
            #pragma unroll
            for (int r = 0; r < 4; r++) acc[mi][ni][r] = 0.f;

    const size_t aoff = (size_t)(bm + sr) * GK + sc;
    const size_t boff = (size_t)(bn + sr) * GK + sc;

    uint4 pa_h = *(const uint4*)(Ahp + aoff);
    uint4 pa_l = *(const uint4*)(Alp + aoff);
    uint4 pb_h = *(const uint4*)(Bhp + boff);
    uint4 pb_l = *(const uint4*)(Blp + boff);
    *(uint4*)&sAh[0][sr][sc] = pa_h;
    *(uint4*)&sAl[0][sr][sc] = pa_l;
    *(uint4*)&sBh[0][sr][sc] = pb_h;
    *(uint4*)&sBl[0][sr][sc] = pb_l;
    __syncthreads();

    const int NT = GK / 16;   // 64
    for (int kt = 0; kt < NT; kt++) {
        const int buf  = kt & 1;
        const int nbuf = buf ^ 1;
        const bool more = (kt + 1) < NT;

        if (more) {
            const size_t ko = (size_t)(kt + 1) * 16;
            pa_h = *(const uint4*)(Ahp + aoff + ko);
            pa_l = *(const uint4*)(Alp + aoff + ko);
            pb_h = *(const uint4*)(Bhp + boff + ko);
            pb_l = *(const uint4*)(Blp + boff + ko);
        }

        uint32_t afh[2][4], afl[2][4];
        #pragma unroll
        for (int mi = 0; mi < 2; mi++) {
            const int r0 = wm + mi * 16 + gid;
            afh[mi][0] = *(const uint32_t*)&sAh[buf][r0    ][2 * tig];
            afh[mi][1] = *(const uint32_t*)&sAh[buf][r0 + 8][2 * tig];
            afh[mi][2] = *(const uint32_t*)&sAh[buf][r0    ][2 * tig + 8];
            afh[mi][3] = *(const uint32_t*)&sAh[buf][r0 + 8][2 * tig + 8];
            afl[mi][0] = *(const uint32_t*)&sAl[buf][r0    ][2 * tig];
            afl[mi][1] = *(const uint32_t*)&sAl[buf][r0 + 8][2 * tig];
            afl[mi][2] = *(const uint32_t*)&sAl[buf][r0    ][2 * tig + 8];
            afl[mi][3] = *(const uint32_t*)&sAl[buf][r0 + 8][2 * tig + 8];
        }
        uint32_t bfh[8][2], bfl[8][2];
        #pragma unroll
        for (int ni = 0; ni < 8; ni++) {
            const int nr = wn + ni * 8 + gid;
            bfh[ni][0] = *(const uint32_t*)&sBh[buf][nr][2 * tig];
            bfh[ni][1] = *(const uint32_t*)&sBh[buf][nr][2 * tig + 8];
            bfl[ni][0] = *(const uint32_t*)&sBl[buf][nr][2 * tig];
            bfl[ni][1] = *(const uint32_t*)&sBl[buf][nr][2 * tig + 8];
        }

        #pragma unroll
        for (int mi = 0; mi < 2; mi++)
            #pragma unroll
            for (int ni = 0; ni < 8; ni++) {
                mma_bf16(acc[mi][ni], afh[mi], bfh[ni]);
                mma_bf16(acc[mi][ni], afh[mi], bfl[ni]);
                mma_bf16(acc[mi][ni], afl[mi], bfh[ni]);
            }

        if (more) {
            *(uint4*)&sAh[nbuf][sr][sc] = pa_h;
            *(uint4*)&sAl[nbuf][sr][sc] = pa_l;
            *(uint4*)&sBh[nbuf][sr][sc] = pb_h;
            *(uint4*)&sBl[nbuf][sr][sc] = pb_l;
        }
        __syncthreads();
    }

    #pragma unroll
    for (int mi = 0; mi < 2; mi++) {
        const int row = bm + wm + mi * 16 + gid;
        #pragma unroll
        for (int ni = 0; ni < 8; ni++) {
            const int col = bn + wn + ni * 8 + 2 * tig;
            *(float2*)(C + (size_t)row * GH + col) =
                make_float2(acc[mi][ni][0], acc[mi][ni][1]);
            *(float2*)(C + (size_t)(row + 8) * GH + col) =
                make_float2(acc[mi][ni][2], acc[mi][ni][3]);
        }
    }
}

// ---------------------------------------------------------------------------
// Fused hyperbolic chain, 3 reduction stages, 256 threads x 4 elems (float4).
// ---------------------------------------------------------------------------

__device__ __forceinline__ float artanh_c(float v) {
    v = fminf(fmaxf(v, -1.0f + 1e-5f), 1.0f - 1e-5f);
    return 0.5f * (log1pf(v) - log1pf(-v));
}
__device__ __forceinline__ float clipn(float s) { return fmaxf(s, 1e-15f); }

// block reduction for 256 threads; sred must hold N*9 floats
template<int N>
__device__ __forceinline__ void bred256(float (&v)[N], float* sred) {
    const int lane = threadIdx.x & 31;
    const int wid  = threadIdx.x >> 5;      // 0..7
    #pragma unroll
    for (int i = 0; i < N; i++) {
        float x = v[i];
        #pragma unroll
        for (int o = 16; o > 0; o >>= 1) x += __shfl_down_sync(0xffffffffu, x, o);
        if (lane == 0) sred[i * 9 + wid] = x;
    }
    __syncthreads();
    if (threadIdx.x < N) {
        float s = 0.f;
        #pragma unroll
        for (int j = 0; j < 8; j++) s += sred[threadIdx.x * 9 + j];
        sred[threadIdx.x * 9 + 8] = s;
    }
    __syncthreads();
    #pragma unroll
    for (int i = 0; i < N; i++) v[i] = sred[i * 9 + 8];
}

__global__ __launch_bounds__(256) void fused2_kernel(
    const float* __restrict__ inp, const float* __restrict__ prevh,
    const float* __restrict__ bz, const float* __restrict__ br,
    const float* __restrict__ bhp, float* __restrict__ out)
{
    const int row = blockIdx.x;
    const int t   = threadIdx.x;
    const size_t base = (size_t)row * GH;
    const size_t S    = (size_t)GB * GH;
    __shared__ float sred[23 * 9];

    float x[4], h[4], xwz[4], hwz[4], xwr[4], hwr[4], xwh[4], hwh[4];
    float vbz[4], vbr[4], vbh[4];
    *(float4*)x   = ((const float4*)(inp   + base))[t];
    *(float4*)h   = ((const float4*)(prevh + base))[t];
    *(float4*)xwz = ((const float4*)(g_mm + 0 * S + base))[t];
    *(float4*)hwz = ((const float4*)(g_mm + 1 * S + base))[t];
    *(float4*)xwr = ((const float4*)(g_mm + 2 * S + base))[t];
    *(float4*)hwr = ((const float4*)(g_mm + 3 * S + base))[t];
    *(float4*)xwh = ((const float4*)(g_mm + 4 * S + base))[t];
    *(float4*)hwh = ((const float4*)(g_mm + 5 * S + base))[t];
    *(float4*)vbz = ((const float4*)bz)[t];
    *(float4*)vbr = ((const float4*)br)[t];
    *(float4*)vbh = ((const float4*)bhp)[t];

    // ---- stage AB: 23 raw sums ------------------------------------------
    float r[23];
    #pragma unroll
    for (int i = 0; i < 23; i++) r[i] = 0.f;
    #pragma unroll
    for (int j = 0; j < 4; j++) {
        r[0]  += x[j]*x[j];       r[1]  += h[j]*h[j];
        r[2]  += xwz[j]*xwz[j];   r[3]  += hwz[j]*hwz[j];
        r[4]  += xwr[j]*xwr[j];   r[5]  += hwr[j]*hwr[j];
        r[6]  += xwh[j]*xwh[j];   r[7]  += hwh[j]*hwh[j];
        r[8]  += xwz[j]*hwz[j];   r[9]  += xwr[j]*hwr[j];
        r[10] += xwh[j]*hwh[j];   r[11] += h[j]*hwh[j];
        r[12] += h[j]*xwh[j];
        r[13] += hwz[j]*vbz[j];   r[14] += vbz[j]*vbz[j];
        r[15] += hwr[j]*vbr[j];   r[16] += vbr[j]*vbr[j];
        r[17] += hwh[j]*vbh[j];   r[18] += vbh[j]*vbh[j];
        r[19] += h[j]*vbh[j];     r[20] += xwh[j]*vbh[j];
        r[21] += xwz[j]*vbz[j];   r[22] += xwr[j]*vbr[j];
    }
    bred256<23>(r, sred);

    const float S1 = r[0], S2 = r[1], S3 = r[2], S4 = r[3], S5 = r[4];
    const float S6 = r[5], S7 = r[6], S8 = r[7];
    const float D1 = r[8], D2 = r[9], D5 = r[12];
    const float E1 = r[13], E2 = r[14], E3 = r[15], E4 = r[16];
    const float E5 = r[17], E6 = r[18];
    const float E9 = r[21], E10 = r[22];

    const float x_n = sqrtf(clipn(S1)), h_n = sqrtf(clipn(S2));
    const float atx = artanh_c(x_n),    ath = artanh_c(h_n);
    const float n_xz = sqrtf(clipn(S3)), n_hz = sqrtf(clipn(S4));
    const float n_xr = sqrtf(clipn(S5)), n_hr = sqrtf(clipn(S6));
    const float n_xh = sqrtf(clipn(S7)), n_hh = sqrtf(clipn(S8));
    const float f_xz = tanhf(n_xz / x_n * atx) / n_xz;
    const float f_hz = tanhf(n_hz / h_n * ath) / n_hz;
    const float f_xr = tanhf(n_xr / x_n * atx) / n_xr;
    const float f_hr = tanhf(n_hr / h_n * ath) / n_hr;
    const float f_xh = tanhf(n_xh / x_n * atx) / n_xh;
    const float f_hh = tanhf(n_hh / h_n * ath) / n_hh;

    // ---- z-branch (closed form through the gate) -------------------------
    float xy, x2, y2, den;
    // inner madd(a_z = f_hz*hWz, Bz)
    xy = f_hz * E1; x2 = f_hz * f_hz * S4; y2 = E2;
    den = 1.f + 2.f * xy + x2 * y2;
    const float czh = ((1.f + 2.f * xy + y2) / den) * f_hz;   // coef on hWz
    const float czb = (1.f - x2) / den;                       // coef on Bz
    const float s_iz = czh*czh*S4 + 2.f*czh*czb*E1 + czb*czb*E2;
    const float d_mz_iz = f_xz * (czh * D1 + czb * E9);
    // outer madd(mvx_z = f_xz*xWz, iz)
    xy = d_mz_iz; x2 = f_xz * f_xz * S3; y2 = s_iz;
    den = 1.f + 2.f * xy + x2 * y2;
    const float pz = (1.f + 2.f * xy + y2) / den;
    const float qz = (1.f - x2) / den;
    const float s_uz = pz*pz*x2 + 2.f*pz*qz*xy + qz*qz*y2;
    const float un_z = sqrtf(clipn(s_uz));
    const float gz_f = artanh_c(un_z) / un_z;

    // ---- r-branch --------------------------------------------------------
    xy = f_hr * E3; x2 = f_hr * f_hr * S6; y2 = E4;
    den = 1.f + 2.f * xy + x2 * y2;
    const float crh = ((1.f + 2.f * xy + y2) / den) * f_hr;
    const float crb = (1.f - x2) / den;
    const float s_ir = crh*crh*S6 + 2.f*crh*crb*E3 + crb*crb*E4;
    const float d_mr_ir = f_xr * (crh * D2 + crb * E10);
    xy = d_mr_ir; x2 = f_xr * f_xr * S5; y2 = s_ir;
    den = 1.f + 2.f * xy + x2 * y2;
    const float pr = (1.f + 2.f * xy + y2) / den;
    const float qr = (1.f - x2) / den;
    const float s_ur = pr*pr*x2 + 2.f*pr*qr*xy + qr*qr*y2;
    const float un_r = sqrtf(clipn(s_ur));
    const float gr_f = artanh_c(un_r) / un_r;

    // ---- h-branch scalars ------------------------------------------------
    xy = f_hh * E5; x2 = f_hh * f_hh * S8; y2 = E6;
    den = 1.f + 2.f * xy + x2 * y2;
    const float ch = ((1.f + 2.f * xy + y2) / den) * f_hh;    // coef on hWh
    const float cb = (1.f - x2) / den;                        // coef on Bh
    const float s_hh = ch*ch*S8 + 2.f*ch*cb*E5 + cb*cb*E6;
    const float hh_n = sqrtf(clipn(s_hh));
    const float at_hh = artanh_c(hh_n);
    const float s_mvxh = f_xh * f_xh * S7;
    const float d_h_mvxh = f_xh * D5;

    // ---- per-element gates + vectors ------------------------------------
    float zg[4], ux[4], mvxh[4];
    #pragma unroll
    for (int j = 0; j < 4; j++) {
        const float iz  = czh * hwz[j] + czb * vbz[j];
        const float uz  = pz * f_xz * xwz[j] + qz * iz;
        zg[j] = 1.f / (1.f + expf(-gz_f * uz));
        const float ir  = crh * hwr[j] + crb * vbr[j];
        const float ur  = pr * f_xr * xwr[j] + qr * ir;
        const float rg  = 1.f / (1.f + expf(-gr_f * ur));
        const float hhj = ch * hwh[j] + cb * vbh[j];
        ux[j]   = rg * hhj;
        mvxh[j] = f_xh * xwh[j];
    }

    // ---- stage C: 3 sums -------------------------------------------------
    float c3[3] = { 0.f, 0.f, 0.f };
    #pragma unroll
    for (int j = 0; j < 4; j++) {
        c3[0] += ux[j] * ux[j];
        c3[1] += ux[j] * mvxh[j];
        c3[2] += h[j]  * ux[j];
    }
    bred256<3>(c3, sred);
    const float C1 = c3[0], C2 = c3[1], C3 = c3[2];

    const float uxn = sqrtf(clipn(C1));
    const float gp  = tanhf(uxn / hh_n * at_hh) / uxn;
    // temp = madd(p = gp*ux, mvx_h)
    xy = gp * C2; x2 = gp * gp * C1; y2 = s_mvxh;
    den = 1.f + 2.f * xy + x2 * y2;
    const float ct = (1.f + 2.f * xy + y2) / den;
    const float dt = (1.f - x2) / den;
    const float s_temp = ct*ct*x2 + 2.f*ct*dt*xy + dt*dt*y2;
    const float d_h_temp = ct * gp * C3 + dt * d_h_mvxh;
    // minus_h = madd(-h, temp)
    xy = -d_h_temp; x2 = S2; y2 = s_temp;
    den = 1.f + 2.f * xy + x2 * y2;
    const float cm = (1.f + 2.f * xy + y2) / den;
    const float dm = (1.f - x2) / den;
    const float s_mh  = cm*cm*S2 - 2.f*cm*dm*d_h_temp + dm*dm*s_temp;
    const float mh_n  = sqrtf(clipn(s_mh));
    const float at_mh = artanh_c(mh_n);

    // ---- stage D: 2 sums -------------------------------------------------
    float uq[4];
    float d2[2] = { 0.f, 0.f };
    #pragma unroll
    for (int j = 0; j < 4; j++) {
        const float tempj = ct * gp * ux[j] + dt * mvxh[j];
        const float mhj   = -cm * h[j] + dm * tempj;
        uq[j] = zg[j] * mhj;
        d2[0] += uq[j] * uq[j];
        d2[1] += h[j]  * uq[j];
    }
    bred256<2>(d2, sred);
    const float F1 = d2[0], F2 = d2[1];

    const float uqn = sqrtf(clipn(F1));
    const float gq  = tanhf(uqn / mh_n * at_mh) / uqn;
    // out = madd(h, q = gq*uq)
    xy = gq * F2; x2 = S2; y2 = gq * gq * F1;
    den = 1.f + 2.f * xy + x2 * y2;
    const float ka = (1.f + 2.f * xy + y2) / den;
    const float kb = (1.f - x2) / den;

    float o[4];
    #pragma unroll
    for (int j = 0; j < 4; j++) o[j] = ka * h[j] + kb * gq * uq[j];
    ((float4*)(out + base))[t] = *(const float4*)o;
}

// ---------------------------------------------------------------------------
extern "C" void kernel_launch(void* const* d_in, const int* in_sizes, int n_in,
                              void* d_out, int out_size)
{
    const float* inp   = (const float*)d_in[0];
    const float* prevh = (const float*)d_in[1];
    const float* wiz   = (const float*)d_in[2];
    const float* whz   = (const float*)d_in[3];
    const float* bz    = (const float*)d_in[4];
    const float* wir   = (const float*)d_in[5];
    const float* whr   = (const float*)d_in[6];
    const float* br    = (const float*)d_in[7];
    const float* wih   = (const float*)d_in[8];
    const float* whh   = (const float*)d_in[9];
    const float* bh    = (const float*)d_in[10];
    float* out = (float*)d_out;

    conv_inputs<<<dim3(GB * GK / 1024, 2), 256>>>(inp, prevh);
    conv_weights<<<dim3(GH / 32, GK / 32, 6), dim3(32, 8)>>>(wiz, whz, wir, whr, wih, whh);
    gemm6_v3<<<dim3(GH / 128, GB / 128, 6), 256>>>();
    fused2_kernel<<<GB, 256>>>(inp, prevh, bz, br, bh, out);
}